// round 12
// baseline (speedup 1.0000x reference)
#include <cuda_runtime.h>
#include <cuda_fp16.h>
#include <cstdint>

#define INV_SCALE 0.35355339059327373f
#define PT_CAP (1 << 20)
#define NB  512     // sort blocks
#define TPB 512     // threads per sort block

// Scratch (allocation-free: __device__ globals).
__device__ float  g_vol32[28 * 32 * 32 * 32];
__device__ float  g_vol64[28 * 64 * 64 * 64];
__device__ __half g_vol128h[128 * 128 * 128 * 28];   // channel-last fp16, 117MB
__device__ unsigned int g_bh[512 * NB];              // per-(bin,block) counts -> row prefixes
__device__ unsigned int g_bintot[512];
__device__ unsigned int g_binbase[512];
__device__ float4 g_sorted[PT_CAP];                  // xyz + orig index

// ---------------------------------------------------------------------------
// Inverse 3D Haar butterfly
// ---------------------------------------------------------------------------
__device__ __forceinline__ void haar_butterfly(
    float a, float d0, float d1, float d2, float d3, float d4, float d5, float d6,
    float o[2][2][2])
{
    float e000 = a  + d0, e001 = a  - d0;
    float e010 = d1 + d2, e011 = d1 - d2;
    float e100 = d3 + d4, e101 = d3 - d4;
    float e110 = d5 + d6, e111 = d5 - d6;
    float f000 = e000 + e010, f010 = e000 - e010;
    float f001 = e001 + e011, f011 = e001 - e011;
    float f100 = e100 + e110, f110 = e100 - e110;
    float f101 = e101 + e111, f111 = e101 - e111;
    o[0][0][0] = (f000 + f100) * INV_SCALE;
    o[0][0][1] = (f001 + f101) * INV_SCALE;
    o[0][1][0] = (f010 + f110) * INV_SCALE;
    o[0][1][1] = (f011 + f111) * INV_SCALE;
    o[1][0][0] = (f000 - f100) * INV_SCALE;
    o[1][0][1] = (f001 - f101) * INV_SCALE;
    o[1][1][0] = (f010 - f110) * INV_SCALE;
    o[1][1][1] = (f011 - f111) * INV_SCALE;
}

// ---------------------------------------------------------------------------
// Levels 0 and 1: channel-major fp32 in/out.
// ---------------------------------------------------------------------------
template <int D>
__global__ void idwt_cm_kernel(const float* __restrict__ approx,
                               const float* __restrict__ det,
                               float* __restrict__ out)
{
    const int D3 = D * D * D;
    int tid = blockIdx.x * blockDim.x + threadIdx.x;
    if (tid >= 28 * D3) return;

    int k = tid % D;
    int j = (tid / D) % D;
    int i = (tid / (D * D)) % D;
    int c = tid / D3;
    int sp = (i * D + j) * D + k;

    float a  = __ldg(&approx[c * D3 + sp]);
    float d0 = __ldg(&det[(0 * 28 + c) * D3 + sp]);
    float d1 = __ldg(&det[(1 * 28 + c) * D3 + sp]);
    float d2 = __ldg(&det[(2 * 28 + c) * D3 + sp]);
    float d3 = __ldg(&det[(3 * 28 + c) * D3 + sp]);
    float d4 = __ldg(&det[(4 * 28 + c) * D3 + sp]);
    float d5 = __ldg(&det[(5 * 28 + c) * D3 + sp]);
    float d6 = __ldg(&det[(6 * 28 + c) * D3 + sp]);

    float o[2][2][2];
    haar_butterfly(a, d0, d1, d2, d3, d4, d5, d6, o);

    const int E = 2 * D;
#pragma unroll
    for (int p = 0; p < 2; ++p)
#pragma unroll
        for (int q = 0; q < 2; ++q) {
            int base = ((c * E + (2 * i + p)) * E + (2 * j + q)) * E + 2 * k;
            *reinterpret_cast<float2*>(&out[base]) =
                make_float2(o[p][q][0], o[p][q][1]);
        }
}

// ---------------------------------------------------------------------------
// Level 2: channel-major 64^3 fp32 -> channel-last 128^3 fp16 via smem.
// ---------------------------------------------------------------------------
__global__ __launch_bounds__(896) void idwt2_kernel(const float* __restrict__ det)
{
    const int D = 64, D3 = D * D * D;
    int ij = blockIdx.x;
    int i = ij / 64;
    int j = ij % 64;
    int c  = threadIdx.x / 32;
    int kl = threadIdx.x % 32;

    __shared__ float sm[4][64 * 29];

    for (int h = 0; h < 2; ++h) {
        int k  = kl + 32 * h;
        int sp = (i * D + j) * D + k;

        float a  = __ldcs(&g_vol64[c * D3 + sp]);
        float d0 = __ldcs(&det[(0 * 28 + c) * D3 + sp]);
        float d1 = __ldcs(&det[(1 * 28 + c) * D3 + sp]);
        float d2 = __ldcs(&det[(2 * 28 + c) * D3 + sp]);
        float d3 = __ldcs(&det[(3 * 28 + c) * D3 + sp]);
        float d4 = __ldcs(&det[(4 * 28 + c) * D3 + sp]);
        float d5 = __ldcs(&det[(5 * 28 + c) * D3 + sp]);
        float d6 = __ldcs(&det[(6 * 28 + c) * D3 + sp]);

        float o[2][2][2];
        haar_butterfly(a, d0, d1, d2, d3, d4, d5, d6, o);

#pragma unroll
        for (int p = 0; p < 2; ++p)
#pragma unroll
            for (int q = 0; q < 2; ++q)
#pragma unroll
                for (int r = 0; r < 2; ++r)
                    sm[p * 2 + q][(2 * kl + r) * 29 + c] = o[p][q][r];

        __syncthreads();

        __half2* vol2 = reinterpret_cast<__half2*>(g_vol128h);
        for (int idx = threadIdx.x; idx < 4 * 64 * 14; idx += 896) {
            int pq   = idx / (64 * 14);
            int rem2 = idx % (64 * 14);
            int x    = rem2 / 14;
            int m    = rem2 % 14;
            int p = pq >> 1, q = pq & 1;
            float lo = sm[pq][x * 29 + 2 * m];
            float hi = sm[pq][x * 29 + 2 * m + 1];
            int base2 = ((((2 * i + p) * 128 + (2 * j + q)) * 128 + 64 * h) * 14);
            vol2[base2 + rem2] = __floats2half2_rn(lo, hi);
        }
        __syncthreads();
    }
}

// ---------------------------------------------------------------------------
// Spatial binning: 8x8x8 = 512 tiles of 16^3 voxels.
// ---------------------------------------------------------------------------
__device__ __forceinline__ int point_bin(float x, float y, float z)
{
    const float S = 127.0f / 3.0f;
    int x0 = (int)floorf(fmaf(x, S, 63.5f));
    int y0 = (int)floorf(fmaf(y, S, 63.5f));
    int z0 = (int)floorf(fmaf(z, S, 63.5f));
    x0 = min(max(x0, 0), 127);
    y0 = min(max(y0, 0), 127);
    z0 = min(max(z0, 0), 127);
    return ((z0 >> 4) << 6) | ((y0 >> 4) << 3) | (x0 >> 4);
}

// Pass 1: per-block shared-memory histogram -> g_bh[bin*NB + block]
__global__ __launch_bounds__(TPB) void hist_kernel(const float* __restrict__ xyz,
                                                   int n, int chunk)
{
    __shared__ unsigned int h[512];
    for (int i = threadIdx.x; i < 512; i += TPB) h[i] = 0;
    __syncthreads();

    int start = blockIdx.x * chunk;
    int end   = min(start + chunk, n);
    for (int p = start + threadIdx.x; p < end; p += TPB) {
        float x = __ldcs(&xyz[3 * p + 0]);
        float y = __ldcs(&xyz[3 * p + 1]);
        float z = __ldcs(&xyz[3 * p + 2]);
        atomicAdd(&h[point_bin(x, y, z)], 1u);
    }
    __syncthreads();
    for (int i = threadIdx.x; i < 512; i += TPB)
        g_bh[i * NB + blockIdx.x] = h[i];
}

// Scan stage A: one block per bin, coalesced row scan.
__global__ __launch_bounds__(NB) void scan_rows_kernel()
{
    __shared__ unsigned int s[NB];
    int bin = blockIdx.x;
    int t = threadIdx.x;
    unsigned int own = g_bh[bin * NB + t];
    s[t] = own;
    __syncthreads();
    for (int d = 1; d < NB; d <<= 1) {
        unsigned int v = (t >= d) ? s[t - d] : 0u;
        __syncthreads();
        s[t] += v;
        __syncthreads();
    }
    g_bh[bin * NB + t] = s[t] - own;
    if (t == NB - 1) g_bintot[bin] = s[t];
}

// Scan stage B: one block over 512 bin totals.
__global__ __launch_bounds__(512) void scan_bins_kernel()
{
    __shared__ unsigned int s[512];
    int t = threadIdx.x;
    unsigned int own = g_bintot[t];
    s[t] = own;
    __syncthreads();
    for (int d = 1; d < 512; d <<= 1) {
        unsigned int v = (t >= d) ? s[t - d] : 0u;
        __syncthreads();
        s[t] += v;
        __syncthreads();
    }
    g_binbase[t] = s[t] - own;
}

// Pass 2: scatter into pre-reserved slots; smem atomics only.
__global__ __launch_bounds__(TPB) void scatter_kernel(const float* __restrict__ xyz,
                                                      int n, int chunk)
{
    __shared__ unsigned int h[512];
    for (int i = threadIdx.x; i < 512; i += TPB)
        h[i] = g_bh[i * NB + blockIdx.x] + g_binbase[i];
    __syncthreads();

    int start = blockIdx.x * chunk;
    int end   = min(start + chunk, n);
    for (int p = start + threadIdx.x; p < end; p += TPB) {
        float x = __ldcs(&xyz[3 * p + 0]);
        float y = __ldcs(&xyz[3 * p + 1]);
        float z = __ldcs(&xyz[3 * p + 2]);
        unsigned int pos = atomicAdd(&h[point_bin(x, y, z)], 1u);
        g_sorted[pos] = make_float4(x, y, z, __int_as_float(p));
    }
}

// ---------------------------------------------------------------------------
// Sampling: ONE point per warp. Lane = dx*14 + channel_pair, so a single
// 28-lane half2 LDG covers BOTH x-corners of one (z,y) slab -> 4 gather
// loads per point, each a contiguous 112B region. x-interpolation folded
// into a lane weight + shfl_down(14) reduction.
// ---------------------------------------------------------------------------
__global__ void sample_sorted_kernel(float* __restrict__ out, int n)
{
    int warp = (blockIdx.x * blockDim.x + threadIdx.x) >> 5;
    int lane = threadIdx.x & 31;
    if (warp >= n || lane >= 28) return;

    int m = (lane < 14) ? lane : lane - 14;   // channel pair index

    float4 pt = __ldg(&g_sorted[warp]);
    int orig = __float_as_int(pt.w);

    const float S = 127.0f / 3.0f;
    float px = fmaf(pt.x, S, 63.5f);
    float py = fmaf(pt.y, S, 63.5f);
    float pz = fmaf(pt.z, S, 63.5f);

    float flx = floorf(px), fly = floorf(py), flz = floorf(pz);
    int x0 = (int)flx, y0 = (int)fly, z0 = (int)flz;
    float fx = px - flx, fy = py - fly, fz = pz - flz;

    // Points are strictly interior for this input; clamps are guards only.
    x0 = min(max(x0, 0), 126);
    y0 = min(max(y0, 0), 126);
    z0 = min(max(z0, 0), 126);

    float wxl = (lane >= 14) ? fx : (1.0f - fx);
    float w00 = (1.0f - fz) * (1.0f - fy);
    float w01 = (1.0f - fz) * fy;
    float w10 = fz * (1.0f - fy);
    float w11 = fz * fy;

    const __half2* __restrict__ vol2 =
        reinterpret_cast<const __half2*>(g_vol128h);

    const int SY = 128 * 14;
    const int SZ = 128 * 128 * 14;
    int base = ((z0 * 128 + y0) * 128 + x0) * 14 + lane;

    float2 a00 = __half22float2(__ldg(&vol2[base]));
    float2 a01 = __half22float2(__ldg(&vol2[base + SY]));
    float2 a10 = __half22float2(__ldg(&vol2[base + SZ]));
    float2 a11 = __half22float2(__ldg(&vol2[base + SZ + SY]));

    float ax = w00 * a00.x;
    float ay = w00 * a00.y;
    ax = fmaf(w01, a01.x, ax);  ay = fmaf(w01, a01.y, ay);
    ax = fmaf(w10, a10.x, ax);  ay = fmaf(w10, a10.y, ay);
    ax = fmaf(w11, a11.x, ax);  ay = fmaf(w11, a11.y, ay);
    ax *= wxl;
    ay *= wxl;

    const unsigned mask = 0x0FFFFFFFu;
    ax += __shfl_down_sync(mask, ax, 14);
    ay += __shfl_down_sync(mask, ay, 14);

    if (lane < 14)
        __stwt(reinterpret_cast<float2*>(&out[(size_t)orig * 28 + 2 * m]),
               make_float2(ax, ay));
}

// Fallback (unsorted, n > PT_CAP): same packed-gather scheme on raw xyz.
__global__ void sample_kernel(const float* __restrict__ xyz,
                              float* __restrict__ out, int n)
{
    int warp = (blockIdx.x * blockDim.x + threadIdx.x) >> 5;
    int lane = threadIdx.x & 31;
    if (warp >= n || lane >= 28) return;

    int m = (lane < 14) ? lane : lane - 14;

    float x = __ldg(&xyz[3 * warp + 0]);
    float y = __ldg(&xyz[3 * warp + 1]);
    float z = __ldg(&xyz[3 * warp + 2]);

    const float S = 127.0f / 3.0f;
    float px = fmaf(x, S, 63.5f);
    float py = fmaf(y, S, 63.5f);
    float pz = fmaf(z, S, 63.5f);

    float flx = floorf(px), fly = floorf(py), flz = floorf(pz);
    int x0 = (int)flx, y0 = (int)fly, z0 = (int)flz;
    float fx = px - flx, fy = py - fly, fz = pz - flz;

    x0 = min(max(x0, 0), 126);
    y0 = min(max(y0, 0), 126);
    z0 = min(max(z0, 0), 126);

    float wxl = (lane >= 14) ? fx : (1.0f - fx);
    float w00 = (1.0f - fz) * (1.0f - fy);
    float w01 = (1.0f - fz) * fy;
    float w10 = fz * (1.0f - fy);
    float w11 = fz * fy;

    const __half2* __restrict__ vol2 =
        reinterpret_cast<const __half2*>(g_vol128h);

    const int SY = 128 * 14;
    const int SZ = 128 * 128 * 14;
    int base = ((z0 * 128 + y0) * 128 + x0) * 14 + lane;

    float2 a00 = __half22float2(__ldg(&vol2[base]));
    float2 a01 = __half22float2(__ldg(&vol2[base + SY]));
    float2 a10 = __half22float2(__ldg(&vol2[base + SZ]));
    float2 a11 = __half22float2(__ldg(&vol2[base + SZ + SY]));

    float ax = w00 * a00.x;
    float ay = w00 * a00.y;
    ax = fmaf(w01, a01.x, ax);  ay = fmaf(w01, a01.y, ay);
    ax = fmaf(w10, a10.x, ax);  ay = fmaf(w10, a10.y, ay);
    ax = fmaf(w11, a11.x, ax);  ay = fmaf(w11, a11.y, ay);
    ax *= wxl;
    ay *= wxl;

    const unsigned mask = 0x0FFFFFFFu;
    ax += __shfl_down_sync(mask, ax, 14);
    ay += __shfl_down_sync(mask, ay, 14);

    if (lane < 14)
        __stwt(reinterpret_cast<float2*>(&out[(size_t)warp * 28 + 2 * m]),
               make_float2(ax, ay));
}

// ---------------------------------------------------------------------------
extern "C" void kernel_launch(void* const* d_in, const int* in_sizes, int n_in,
                              void* d_out, int out_size)
{
    const float* approx    = (const float*)d_in[0];
    const float* details_0 = (const float*)d_in[1];
    const float* details_1 = (const float*)d_in[2];
    const float* details_2 = (const float*)d_in[3];
    const float* xyz       = (const float*)d_in[4];
    float* out             = (float*)d_out;

    int n = in_sizes[4] / 3;

    float* p32 = nullptr;
    float* p64 = nullptr;
    cudaGetSymbolAddress((void**)&p32, g_vol32);
    cudaGetSymbolAddress((void**)&p64, g_vol64);

    // Reconstruction
    {
        int nthreads = 28 * 16 * 16 * 16;
        idwt_cm_kernel<16><<<(nthreads + 255) / 256, 256>>>(approx, details_0, p32);
    }
    {
        int nthreads = 28 * 32 * 32 * 32;
        idwt_cm_kernel<32><<<(nthreads + 255) / 256, 256>>>(p32, details_1, p64);
    }
    idwt2_kernel<<<64 * 64, 896>>>(details_2);

    if (n <= PT_CAP) {
        int chunk = (n + NB - 1) / NB;
        hist_kernel<<<NB, TPB>>>(xyz, n, chunk);
        scan_rows_kernel<<<512, NB>>>();
        scan_bins_kernel<<<1, 512>>>();
        scatter_kernel<<<NB, TPB>>>(xyz, n, chunk);
        int blocks = (n + 7) / 8;   // 8 warps (points) per 256-thread block
        sample_sorted_kernel<<<blocks, 256>>>(out, n);
    } else {
        int blocks = (n + 7) / 8;
        sample_kernel<<<blocks, 256>>>(xyz, out, n);
    }
}

// round 16
// speedup vs baseline: 1.2863x; 1.2863x over previous
#include <cuda_runtime.h>
#include <cuda_fp16.h>
#include <cstdint>

#define INV_SCALE 0.35355339059327373f
#define PT_CAP (1 << 20)
#define NB  512     // sort blocks
#define TPB 512     // threads per sort block

// Scratch (allocation-free: __device__ globals).
__device__ float  g_vol32[28 * 32 * 32 * 32];
__device__ float  g_vol64[28 * 64 * 64 * 64];
__device__ __half g_vol128h[128 * 128 * 128 * 28];   // channel-last fp16, 117MB
__device__ unsigned int g_bh[512 * NB];              // per-(bin,block) counts -> row prefixes
__device__ unsigned int g_bintot[512];
__device__ unsigned int g_binbase[512];
__device__ float4 g_sorted[PT_CAP];                  // xyz + orig index

// ---------------------------------------------------------------------------
// Inverse 3D Haar butterfly
// ---------------------------------------------------------------------------
__device__ __forceinline__ void haar_butterfly(
    float a, float d0, float d1, float d2, float d3, float d4, float d5, float d6,
    float o[2][2][2])
{
    float e000 = a  + d0, e001 = a  - d0;
    float e010 = d1 + d2, e011 = d1 - d2;
    float e100 = d3 + d4, e101 = d3 - d4;
    float e110 = d5 + d6, e111 = d5 - d6;
    float f000 = e000 + e010, f010 = e000 - e010;
    float f001 = e001 + e011, f011 = e001 - e011;
    float f100 = e100 + e110, f110 = e100 - e110;
    float f101 = e101 + e111, f111 = e101 - e111;
    o[0][0][0] = (f000 + f100) * INV_SCALE;
    o[0][0][1] = (f001 + f101) * INV_SCALE;
    o[0][1][0] = (f010 + f110) * INV_SCALE;
    o[0][1][1] = (f011 + f111) * INV_SCALE;
    o[1][0][0] = (f000 - f100) * INV_SCALE;
    o[1][0][1] = (f001 - f101) * INV_SCALE;
    o[1][1][0] = (f010 - f110) * INV_SCALE;
    o[1][1][1] = (f011 - f111) * INV_SCALE;
}

// ---------------------------------------------------------------------------
// Levels 0 and 1: channel-major fp32 in/out.
// ---------------------------------------------------------------------------
template <int D>
__global__ void idwt_cm_kernel(const float* __restrict__ approx,
                               const float* __restrict__ det,
                               float* __restrict__ out)
{
    const int D3 = D * D * D;
    int tid = blockIdx.x * blockDim.x + threadIdx.x;
    if (tid >= 28 * D3) return;

    int k = tid % D;
    int j = (tid / D) % D;
    int i = (tid / (D * D)) % D;
    int c = tid / D3;
    int sp = (i * D + j) * D + k;

    float a  = __ldg(&approx[c * D3 + sp]);
    float d0 = __ldg(&det[(0 * 28 + c) * D3 + sp]);
    float d1 = __ldg(&det[(1 * 28 + c) * D3 + sp]);
    float d2 = __ldg(&det[(2 * 28 + c) * D3 + sp]);
    float d3 = __ldg(&det[(3 * 28 + c) * D3 + sp]);
    float d4 = __ldg(&det[(4 * 28 + c) * D3 + sp]);
    float d5 = __ldg(&det[(5 * 28 + c) * D3 + sp]);
    float d6 = __ldg(&det[(6 * 28 + c) * D3 + sp]);

    float o[2][2][2];
    haar_butterfly(a, d0, d1, d2, d3, d4, d5, d6, o);

    const int E = 2 * D;
#pragma unroll
    for (int p = 0; p < 2; ++p)
#pragma unroll
        for (int q = 0; q < 2; ++q) {
            int base = ((c * E + (2 * i + p)) * E + (2 * j + q)) * E + 2 * k;
            *reinterpret_cast<float2*>(&out[base]) =
                make_float2(o[p][q][0], o[p][q][1]);
        }
}

// ---------------------------------------------------------------------------
// Level 2: channel-major 64^3 fp32 -> channel-last 128^3 fp16 via smem.
// ---------------------------------------------------------------------------
__global__ __launch_bounds__(896) void idwt2_kernel(const float* __restrict__ det)
{
    const int D = 64, D3 = D * D * D;
    int ij = blockIdx.x;
    int i = ij / 64;
    int j = ij % 64;
    int c  = threadIdx.x / 32;
    int kl = threadIdx.x % 32;

    __shared__ float sm[4][64 * 29];

    for (int h = 0; h < 2; ++h) {
        int k  = kl + 32 * h;
        int sp = (i * D + j) * D + k;

        float a  = __ldcs(&g_vol64[c * D3 + sp]);
        float d0 = __ldcs(&det[(0 * 28 + c) * D3 + sp]);
        float d1 = __ldcs(&det[(1 * 28 + c) * D3 + sp]);
        float d2 = __ldcs(&det[(2 * 28 + c) * D3 + sp]);
        float d3 = __ldcs(&det[(3 * 28 + c) * D3 + sp]);
        float d4 = __ldcs(&det[(4 * 28 + c) * D3 + sp]);
        float d5 = __ldcs(&det[(5 * 28 + c) * D3 + sp]);
        float d6 = __ldcs(&det[(6 * 28 + c) * D3 + sp]);

        float o[2][2][2];
        haar_butterfly(a, d0, d1, d2, d3, d4, d5, d6, o);

#pragma unroll
        for (int p = 0; p < 2; ++p)
#pragma unroll
            for (int q = 0; q < 2; ++q)
#pragma unroll
                for (int r = 0; r < 2; ++r)
                    sm[p * 2 + q][(2 * kl + r) * 29 + c] = o[p][q][r];

        __syncthreads();

        __half2* vol2 = reinterpret_cast<__half2*>(g_vol128h);
        for (int idx = threadIdx.x; idx < 4 * 64 * 14; idx += 896) {
            int pq   = idx / (64 * 14);
            int rem2 = idx % (64 * 14);
            int x    = rem2 / 14;
            int m    = rem2 % 14;
            int p = pq >> 1, q = pq & 1;
            float lo = sm[pq][x * 29 + 2 * m];
            float hi = sm[pq][x * 29 + 2 * m + 1];
            int base2 = ((((2 * i + p) * 128 + (2 * j + q)) * 128 + 64 * h) * 14);
            vol2[base2 + rem2] = __floats2half2_rn(lo, hi);
        }
        __syncthreads();
    }
}

// ---------------------------------------------------------------------------
// Spatial binning: 8x8x8 = 512 tiles of 16^3 voxels.
// ---------------------------------------------------------------------------
__device__ __forceinline__ int point_bin(float x, float y, float z)
{
    const float S = 127.0f / 3.0f;
    int x0 = (int)floorf(fmaf(x, S, 63.5f));
    int y0 = (int)floorf(fmaf(y, S, 63.5f));
    int z0 = (int)floorf(fmaf(z, S, 63.5f));
    x0 = min(max(x0, 0), 127);
    y0 = min(max(y0, 0), 127);
    z0 = min(max(z0, 0), 127);
    return ((z0 >> 4) << 6) | ((y0 >> 4) << 3) | (x0 >> 4);
}

// Pass 1: per-block shared-memory histogram -> g_bh[bin*NB + block]
__global__ __launch_bounds__(TPB) void hist_kernel(const float* __restrict__ xyz,
                                                   int n, int chunk)
{
    __shared__ unsigned int h[512];
    for (int i = threadIdx.x; i < 512; i += TPB) h[i] = 0;
    __syncthreads();

    int start = blockIdx.x * chunk;
    int end   = min(start + chunk, n);
    for (int p = start + threadIdx.x; p < end; p += TPB) {
        float x = __ldcs(&xyz[3 * p + 0]);
        float y = __ldcs(&xyz[3 * p + 1]);
        float z = __ldcs(&xyz[3 * p + 2]);
        atomicAdd(&h[point_bin(x, y, z)], 1u);
    }
    __syncthreads();
    for (int i = threadIdx.x; i < 512; i += TPB)
        g_bh[i * NB + blockIdx.x] = h[i];
}

// Scan stage A: one block per bin, coalesced row scan.
__global__ __launch_bounds__(NB) void scan_rows_kernel()
{
    __shared__ unsigned int s[NB];
    int bin = blockIdx.x;
    int t = threadIdx.x;
    unsigned int own = g_bh[bin * NB + t];
    s[t] = own;
    __syncthreads();
    for (int d = 1; d < NB; d <<= 1) {
        unsigned int v = (t >= d) ? s[t - d] : 0u;
        __syncthreads();
        s[t] += v;
        __syncthreads();
    }
    g_bh[bin * NB + t] = s[t] - own;
    if (t == NB - 1) g_bintot[bin] = s[t];
}

// Scan stage B: one block over 512 bin totals.
__global__ __launch_bounds__(512) void scan_bins_kernel()
{
    __shared__ unsigned int s[512];
    int t = threadIdx.x;
    unsigned int own = g_bintot[t];
    s[t] = own;
    __syncthreads();
    for (int d = 1; d < 512; d <<= 1) {
        unsigned int v = (t >= d) ? s[t - d] : 0u;
        __syncthreads();
        s[t] += v;
        __syncthreads();
    }
    g_binbase[t] = s[t] - own;
}

// Pass 2: scatter into pre-reserved slots; smem atomics only.
__global__ __launch_bounds__(TPB) void scatter_kernel(const float* __restrict__ xyz,
                                                      int n, int chunk)
{
    __shared__ unsigned int h[512];
    for (int i = threadIdx.x; i < 512; i += TPB)
        h[i] = g_bh[i * NB + blockIdx.x] + g_binbase[i];
    __syncthreads();

    int start = blockIdx.x * chunk;
    int end   = min(start + chunk, n);
    for (int p = start + threadIdx.x; p < end; p += TPB) {
        float x = __ldcs(&xyz[3 * p + 0]);
        float y = __ldcs(&xyz[3 * p + 1]);
        float z = __ldcs(&xyz[3 * p + 2]);
        unsigned int pos = atomicAdd(&h[point_bin(x, y, z)], 1u);
        g_sorted[pos] = make_float4(x, y, z, __int_as_float(p));
    }
}

// ---------------------------------------------------------------------------
// Sampling core: TWO points per warp (one per half-warp) with packed-x
// gathers. Lane t = lane&15; dx = t/7, q = t%7 (4 channels per lane, uint2 =
// 4 halfs). One gather LDG per (dz,dy): 14 lanes x 8B = 112B contiguous
// covering BOTH x-corners. dx folded via lane weight + shfl_down(7, width 16).
// Lanes t in {14,15} are clamped duplicates of t=13 (kept active so the
// full-mask shfl is defined); they never store.
// ---------------------------------------------------------------------------
__device__ __forceinline__ void sample_point_packed(
    float x, float y, float z, int orig, int lane, bool valid,
    float* __restrict__ out)
{
    int t = lane & 15;
    int tc = (t > 13) ? 13 : t;
    int dx = tc / 7;          // 0 or 1
    int q  = tc % 7;          // channel quad (channels 4q..4q+3)

    const float S = 127.0f / 3.0f;
    float px = fmaf(x, S, 63.5f);
    float py = fmaf(y, S, 63.5f);
    float pz = fmaf(z, S, 63.5f);

    float flx = floorf(px), fly = floorf(py), flz = floorf(pz);
    int x0 = (int)flx, y0 = (int)fly, z0 = (int)flz;
    float fx = px - flx, fy = py - fly, fz = pz - flz;

    // Points are strictly interior for this input; clamps are guards only.
    x0 = min(max(x0, 0), 126);
    y0 = min(max(y0, 0), 126);
    z0 = min(max(z0, 0), 126);

    float wxl = dx ? fx : (1.0f - fx);
    float w00 = (1.0f - fz) * (1.0f - fy);
    float w01 = (1.0f - fz) * fy;
    float w10 = fz * (1.0f - fy);
    float w11 = fz * fy;

    // uint2 view: 7 uint2 per voxel (28 halfs = 56B).
    const uint2* __restrict__ vol4 = reinterpret_cast<const uint2*>(g_vol128h);
    int vox = ((z0 * 128 + y0) * 128 + x0) + dx;
    int b   = vox * 7 + q;
    const int SY = 128 * 7;
    const int SZ = 128 * 128 * 7;

    uint2 r00 = __ldg(&vol4[b]);
    uint2 r01 = __ldg(&vol4[b + SY]);
    uint2 r10 = __ldg(&vol4[b + SZ]);
    uint2 r11 = __ldg(&vol4[b + SZ + SY]);

    float a0 = 0.f, a1 = 0.f, a2 = 0.f, a3 = 0.f;
#define ACC4(r, w) do {                                                     \
        __half2 _h0 = *reinterpret_cast<const __half2*>(&(r).x);            \
        __half2 _h1 = *reinterpret_cast<const __half2*>(&(r).y);            \
        float2 _f0 = __half22float2(_h0);                                   \
        float2 _f1 = __half22float2(_h1);                                   \
        a0 = fmaf((w), _f0.x, a0);  a1 = fmaf((w), _f0.y, a1);              \
        a2 = fmaf((w), _f1.x, a2);  a3 = fmaf((w), _f1.y, a3);              \
    } while (0)
    ACC4(r00, w00);
    ACC4(r01, w01);
    ACC4(r10, w10);
    ACC4(r11, w11);
#undef ACC4
    a0 *= wxl; a1 *= wxl; a2 *= wxl; a3 *= wxl;

    // Fold dx: within each 16-lane group, lanes 0-6 += lanes 7-13.
    a0 += __shfl_down_sync(0xFFFFFFFFu, a0, 7, 16);
    a1 += __shfl_down_sync(0xFFFFFFFFu, a1, 7, 16);
    a2 += __shfl_down_sync(0xFFFFFFFFu, a2, 7, 16);
    a3 += __shfl_down_sync(0xFFFFFFFFu, a3, 7, 16);

    if (valid && t < 7) {
        float4* o4 = reinterpret_cast<float4*>(out);
        __stwt(&o4[(size_t)orig * 7 + q], make_float4(a0, a1, a2, a3));
    }
}

__global__ void sample_sorted_kernel(float* __restrict__ out, int n)
{
    int warp = (blockIdx.x * blockDim.x + threadIdx.x) >> 5;
    int lane = threadIdx.x & 31;
    int sub  = lane >> 4;
    int sp   = warp * 2 + sub;
    bool valid = (sp < n);
    int spc = valid ? sp : 0;

    float4 pt = __ldg(&g_sorted[spc]);
    int orig = __float_as_int(pt.w);

    sample_point_packed(pt.x, pt.y, pt.z, orig, lane, valid, out);
}

// Fallback (unsorted, n > PT_CAP): same packed scheme on raw xyz.
__global__ void sample_kernel(const float* __restrict__ xyz,
                              float* __restrict__ out, int n)
{
    int warp = (blockIdx.x * blockDim.x + threadIdx.x) >> 5;
    int lane = threadIdx.x & 31;
    int sub  = lane >> 4;
    int p    = warp * 2 + sub;
    bool valid = (p < n);
    int pc = valid ? p : 0;

    float x = __ldg(&xyz[3 * pc + 0]);
    float y = __ldg(&xyz[3 * pc + 1]);
    float z = __ldg(&xyz[3 * pc + 2]);

    sample_point_packed(x, y, z, pc, lane, valid, out);
}

// ---------------------------------------------------------------------------
extern "C" void kernel_launch(void* const* d_in, const int* in_sizes, int n_in,
                              void* d_out, int out_size)
{
    const float* approx    = (const float*)d_in[0];
    const float* details_0 = (const float*)d_in[1];
    const float* details_1 = (const float*)d_in[2];
    const float* details_2 = (const float*)d_in[3];
    const float* xyz       = (const float*)d_in[4];
    float* out             = (float*)d_out;

    int n = in_sizes[4] / 3;

    float* p32 = nullptr;
    float* p64 = nullptr;
    cudaGetSymbolAddress((void**)&p32, g_vol32);
    cudaGetSymbolAddress((void**)&p64, g_vol64);

    // Reconstruction
    {
        int nthreads = 28 * 16 * 16 * 16;
        idwt_cm_kernel<16><<<(nthreads + 255) / 256, 256>>>(approx, details_0, p32);
    }
    {
        int nthreads = 28 * 32 * 32 * 32;
        idwt_cm_kernel<32><<<(nthreads + 255) / 256, 256>>>(p32, details_1, p64);
    }
    idwt2_kernel<<<64 * 64, 896>>>(details_2);

    if (n <= PT_CAP) {
        int chunk = (n + NB - 1) / NB;
        hist_kernel<<<NB, TPB>>>(xyz, n, chunk);
        scan_rows_kernel<<<512, NB>>>();
        scan_bins_kernel<<<1, 512>>>();
        scatter_kernel<<<NB, TPB>>>(xyz, n, chunk);
        int blocks = (n + 15) / 16;   // 16 points per 256-thread block
        sample_sorted_kernel<<<blocks, 256>>>(out, n);
    } else {
        int blocks = (n + 15) / 16;
        sample_kernel<<<blocks, 256>>>(xyz, out, n);
    }
}